// round 15
// baseline (speedup 1.0000x reference)
#include <cuda_runtime.h>
#include <cuda_fp16.h>
#include <cstdint>

#define NTOK 64
#define HEADS 8
#define HD 32
#define DIM 256

typedef unsigned long long ull;

// bias in MMA-fragment layout (float2 units): [h][row8(8)][r0(8)][c2p(4)][nt(8)]
__device__ float g_bias[HEADS * NTOK * NTOK];

// ---------------- packed helpers ----------------
__device__ __forceinline__ ull ffma2(ull a, ull b, ull c) {
    ull d; asm("fma.rn.f32x2 %0, %1, %2, %3;" : "=l"(d) : "l"(a), "l"(b), "l"(c)); return d;
}
__device__ __forceinline__ ull dup2(float p) {
    ull r; asm("mov.b64 %0, {%1, %1};" : "=l"(r) : "f"(p)); return r;
}
__device__ __forceinline__ float2 u2f2(ull v) {
    float2 r; asm("mov.b64 {%0, %1}, %2;" : "=f"(r.x), "=f"(r.y) : "l"(v)); return r;
}
// fp16 pack: lo element in low half
__device__ __forceinline__ uint32_t f16pack(float lo, float hi) {
    uint32_t r; asm("cvt.rn.f16x2.f32 %0, %1, %2;" : "=r"(r) : "f"(hi), "f"(lo)); return r;
}
// fp16 hi/lo split of a float pair
__device__ __forceinline__ void split2h(float a0, float a1, uint32_t& hi, uint32_t& lo) {
    __half2 h = __float22half2_rn(make_float2(a0, a1));
    float2 back = __half22float2(h);
    __half2 l = __float22half2_rn(make_float2(a0 - back.x, a1 - back.y));
    hi = *reinterpret_cast<uint32_t*>(&h);
    lo = *reinterpret_cast<uint32_t*>(&l);
}
__device__ __forceinline__ uint32_t smem_u32(const void* p) {
    uint32_t a;
    asm("{ .reg .u64 t; cvta.to.shared.u64 t, %1; cvt.u32.u64 %0, t; }" : "=r"(a) : "l"(p));
    return a;
}
__device__ __forceinline__ float2 shfl_xor_f2(float2 v, int m) {
    v.x = __shfl_xor_sync(0xffffffffu, v.x, m);
    v.y = __shfl_xor_sync(0xffffffffu, v.y, m);
    return v;
}
// 4x4 transpose across lane-quads: lane (quad, j) reg s  <-  lane (quad, s) reg j
__device__ __forceinline__ void quad_transpose(float2 f[4], int lane) {
    float2 s, r;
    s = (lane & 1) ? f[0] : f[1]; r = shfl_xor_f2(s, 1);
    if (lane & 1) f[0] = r; else f[1] = r;
    s = (lane & 1) ? f[2] : f[3]; r = shfl_xor_f2(s, 1);
    if (lane & 1) f[2] = r; else f[3] = r;
    s = (lane & 2) ? f[0] : f[2]; r = shfl_xor_f2(s, 2);
    if (lane & 2) f[0] = r; else f[2] = r;
    s = (lane & 2) ? f[1] : f[3]; r = shfl_xor_f2(s, 2);
    if (lane & 2) f[1] = r; else f[3] = r;
}

// ---------------- warp-mma primitives (baseline ISA) ----------------
__device__ __forceinline__ void ldsm4(uint32_t r[4], uint32_t a) {
    asm volatile("ldmatrix.sync.aligned.m8n8.x4.shared.b16 {%0,%1,%2,%3}, [%4];"
        : "=r"(r[0]), "=r"(r[1]), "=r"(r[2]), "=r"(r[3]) : "r"(a));
}
__device__ __forceinline__ void ldsm4t(uint32_t r[4], uint32_t a) {
    asm volatile("ldmatrix.sync.aligned.m8n8.x4.trans.shared.b16 {%0,%1,%2,%3}, [%4];"
        : "=r"(r[0]), "=r"(r[1]), "=r"(r[2]), "=r"(r[3]) : "r"(a));
}
__device__ __forceinline__ void mma16816h(float* c, const uint32_t* a, uint32_t b0, uint32_t b1) {
    asm volatile("mma.sync.aligned.m16n8k16.row.col.f32.f16.f16.f32 "
        "{%0,%1,%2,%3}, {%4,%5,%6,%7}, {%8,%9}, {%0,%1,%2,%3};"
        : "+f"(c[0]), "+f"(c[1]), "+f"(c[2]), "+f"(c[3])
        : "r"(a[0]), "r"(a[1]), "r"(a[2]), "r"(a[3]), "r"(b0), "r"(b1));
}

// smem tile geometry: [64 rows][80B rows]; chunks 0..3 (16B),
// stored at chunk' = chunk ^ ((row>>3)&3) -> conflict-free STS + LDSM.
#define Q_OFF 0
#define K_OFF 5120
#define V_OFF 10240
#define SMEM_TOTAL 15360

__device__ __forceinline__ uint32_t faddr(uint32_t base, int rowbase, int c0, int lane) {
    int row = rowbase + (lane & 15);
    int chunk = (c0 + (lane >> 4)) ^ ((row >> 3) & 3);
    return base + row * 80 + chunk * 16;
}

// ---------------------------------------------------------------------------
// Kernel 1: relative-position bias MLP -> g_bias (fragment layout), 2-way k-split
// ---------------------------------------------------------------------------
__global__ __launch_bounds__(256)
void bias_kernel(const float* __restrict__ rel_pos,
                 const float* __restrict__ w1,
                 const float* __restrict__ b1,
                 const float* __restrict__ w2,
                 const float* __restrict__ b2) {
    __shared__ float w1a[256], w1b[256], b1s[256];
    __shared__ float4 w2s[512];
    const int t = threadIdx.x;
    w1a[t] = w1[t];
    w1b[t] = w1[256 + t];
    b1s[t] = b1[t];
#pragma unroll
    for (int i = t; i < 512; i += 256)
        w2s[i] = ((const float4*)w2)[i];
    __syncthreads();

    const int half = t & 1;
    const int nm = blockIdx.x * 128 + (t >> 1);
    const int n = nm >> 6, m = nm & 63;
    const float r0 = rel_pos[2 * nm];
    const float r1 = rel_pos[2 * nm + 1];
    ull acc[4] = {0ull, 0ull, 0ull, 0ull};
    const ulonglong2* w2u = (const ulonglong2*)w2s;
    const int k0 = half * 128;
#pragma unroll 8
    for (int kk = 0; kk < 128; kk++) {
        const int k = k0 + kk;
        float hk = fmaxf(fmaf(r0, w1a[k], fmaf(r1, w1b[k], b1s[k])), 0.f);
        ull hd = dup2(hk);
        ulonglong2 wa = w2u[2 * k];
        ulonglong2 wb = w2u[2 * k + 1];
        acc[0] = ffma2(hd, wa.x, acc[0]);
        acc[1] = ffma2(hd, wa.y, acc[1]);
        acc[2] = ffma2(hd, wb.x, acc[2]);
        acc[3] = ffma2(hd, wb.y, acc[3]);
    }
    float s[8];
#pragma unroll
    for (int p = 0; p < 4; p++) {
        float2 v = u2f2(acc[p]);
        s[2 * p] = v.x;
        s[2 * p + 1] = v.y;
    }
#pragma unroll
    for (int p = 0; p < 8; p++)
        s[p] += __shfl_xor_sync(0xffffffffu, s[p], 1);
    if (!half) {
        // fragment layout (float units): f2 = ((n>>3)*8 + (n&7))*32 + ((m&7)>>1)*8 + (m>>3)
        const int fi = (((n >> 3) * 8 + (n & 7)) * 32 + ((m & 7) >> 1) * 8 + (m >> 3)) * 2 + (m & 1);
#pragma unroll
        for (int p = 0; p < 8; p++)
            g_bias[p * (NTOK * NTOK) + fi] = s[p] + b2[p];
    }
}

// ---------------------------------------------------------------------------
// Kernel 2: warp-mma attention. CTA=(b,h,branch), 4 warps = 4 m-quarters.
// S: single-fp16 (1 product). PV: P fp16 hi/lo x fp16 V (2 products).
// Bias float4 fragment loads; quad-transposed STG.128 epilogue.
// ---------------------------------------------------------------------------
__global__ __launch_bounds__(128, 6)
void attn_kernel(const float* __restrict__ qkv,
                 const float* __restrict__ ass_qkv,
                 float* __restrict__ out, int B) {
    extern __shared__ char sm[];
    const int b = blockIdx.y;
    const int h = blockIdx.x >> 1;
    const int branch = blockIdx.x & 1;
    const int t = threadIdx.x;
    const int lane = t & 31, w = t >> 5;
    const float scale = 0.17677669529663687f;

    // ---- cooperative gmem -> smem (uniform fp16 pack, swizzled) ----
    {
        const float* srcb = (branch ? ass_qkv : qkv) + (size_t)b * (NTOK * 3 * DIM) + h * HD;
        const int f = t & 7;
        const int tokbase = t >> 3;          // 0..15
#pragma unroll
        for (int it = 0; it < 12; it++) {
            const int mat = it >> 2;
            const int tok = (it & 3) * 16 + tokbase;
            const float4 v = *(const float4*)(srcb + tok * (3 * DIM) + mat * DIM + f * 4);
            const int off = tok * 80 + 16 * ((f >> 1) ^ ((tok >> 3) & 3)) + 8 * (f & 1);
            uint32_t v01 = f16pack(v.x, v.y);
            uint32_t v23 = f16pack(v.z, v.w);
            *(uint2*)(sm + mat * 5120 + off) = make_uint2(v01, v23);
        }
    }
    __syncthreads();

    const int mb = w * 16;           // m-quarter base row
    const uint32_t sbase = smem_u32(sm);
    const uint32_t qq = sbase + Q_OFF;
    const uint32_t kk_ = sbase + K_OFF;
    const uint32_t vv = sbase + V_OFF;

    // ---- S = q @ k^T : 1 m16-tile x 8 n8-tiles, single fp16 product ----
    float sacc[8][4];
#pragma unroll
    for (int nt = 0; nt < 8; nt++)
#pragma unroll
        for (int c = 0; c < 4; c++) sacc[nt][c] = 0.f;

#pragma unroll
    for (int ks = 0; ks < 2; ks++) {
        uint32_t a4[4];
        ldsm4(a4, faddr(qq, mb, 2 * ks, lane));
#pragma unroll
        for (int g = 0; g < 4; g++) {
            uint32_t b4[4];
            ldsm4(b4, faddr(kk_, 16 * g, 2 * ks, lane));
            mma16816h(sacc[2 * g], a4, b4[0], b4[2]);
            mma16816h(sacc[2 * g + 1], a4, b4[1], b4[3]);
        }
    }

    // ---- bias (fragment layout, float4) + scale fold + softmax ----
    const int r0 = lane >> 2, c2 = (lane & 3) * 2;
    float inva, invb;
    {
        const float4* bp4 = (const float4*)(g_bias + h * (NTOK * NTOK))
                            + ((mb >> 3) * 8 + r0) * 16 + (lane & 3) * 4;
        float mxa = -1e30f, mxb = -1e30f;
#pragma unroll
        for (int i = 0; i < 4; i++) {
            float4 bA = __ldg(bp4 + i);
            float4 bB = __ldg(bp4 + 128 + i);
            const int n0 = 2 * i, n1 = 2 * i + 1;
            sacc[n0][0] = fmaf(sacc[n0][0], scale, bA.x);
            sacc[n0][1] = fmaf(sacc[n0][1], scale, bA.y);
            sacc[n1][0] = fmaf(sacc[n1][0], scale, bA.z);
            sacc[n1][1] = fmaf(sacc[n1][1], scale, bA.w);
            sacc[n0][2] = fmaf(sacc[n0][2], scale, bB.x);
            sacc[n0][3] = fmaf(sacc[n0][3], scale, bB.y);
            sacc[n1][2] = fmaf(sacc[n1][2], scale, bB.z);
            sacc[n1][3] = fmaf(sacc[n1][3], scale, bB.w);
            mxa = fmaxf(mxa, fmaxf(fmaxf(sacc[n0][0], sacc[n0][1]), fmaxf(sacc[n1][0], sacc[n1][1])));
            mxb = fmaxf(mxb, fmaxf(fmaxf(sacc[n0][2], sacc[n0][3]), fmaxf(sacc[n1][2], sacc[n1][3])));
        }
        mxa = fmaxf(mxa, __shfl_xor_sync(0xffffffffu, mxa, 1));
        mxa = fmaxf(mxa, __shfl_xor_sync(0xffffffffu, mxa, 2));
        mxb = fmaxf(mxb, __shfl_xor_sync(0xffffffffu, mxb, 1));
        mxb = fmaxf(mxb, __shfl_xor_sync(0xffffffffu, mxb, 2));
        float sa = 0.f, sb = 0.f;
#pragma unroll
        for (int nt = 0; nt < 8; nt++) {
            sacc[nt][0] = __expf(sacc[nt][0] - mxa);
            sacc[nt][1] = __expf(sacc[nt][1] - mxa);
            sacc[nt][2] = __expf(sacc[nt][2] - mxb);
            sacc[nt][3] = __expf(sacc[nt][3] - mxb);
            sa += sacc[nt][0] + sacc[nt][1];
            sb += sacc[nt][2] + sacc[nt][3];
        }
        sa += __shfl_xor_sync(0xffffffffu, sa, 1);
        sa += __shfl_xor_sync(0xffffffffu, sa, 2);
        sb += __shfl_xor_sync(0xffffffffu, sb, 1);
        sb += __shfl_xor_sync(0xffffffffu, sb, 2);
        inva = __fdividef(1.0f, sa);
        invb = __fdividef(1.0f, sb);
    }

    // ---- O = P @ V : P fp16 hi/lo from registers, V fp16 via ldsm.trans ----
    float oacc[4][4];
#pragma unroll
    for (int dt = 0; dt < 4; dt++)
#pragma unroll
        for (int c = 0; c < 4; c++) oacc[dt][c] = 0.f;

#pragma unroll
    for (int kk = 0; kk < 4; kk++) {
        uint32_t ph[4], pl[4];
        split2h(sacc[2 * kk][0], sacc[2 * kk][1], ph[0], pl[0]);
        split2h(sacc[2 * kk][2], sacc[2 * kk][3], ph[1], pl[1]);
        split2h(sacc[2 * kk + 1][0], sacc[2 * kk + 1][1], ph[2], pl[2]);
        split2h(sacc[2 * kk + 1][2], sacc[2 * kk + 1][3], ph[3], pl[3]);
#pragma unroll
        for (int dg = 0; dg < 2; dg++) {
            uint32_t v4[4];
            ldsm4t(v4, faddr(vv, 16 * kk, 2 * dg, lane));
            mma16816h(oacc[2 * dg], ph, v4[0], v4[1]);
            mma16816h(oacc[2 * dg + 1], ph, v4[2], v4[3]);
            mma16816h(oacc[2 * dg], pl, v4[0], v4[1]);
            mma16816h(oacc[2 * dg + 1], pl, v4[2], v4[3]);
        }
    }

    // ---- normalize + quad-transpose + coalesced STG.128 store ----
    {
        float2 fA[4], fB[4];
#pragma unroll
        for (int dt = 0; dt < 4; dt++) {
            fA[dt] = make_float2(oacc[dt][0] * inva, oacc[dt][1] * inva);
            fB[dt] = make_float2(oacc[dt][2] * invb, oacc[dt][3] * invb);
        }
        quad_transpose(fA, lane);
        quad_transpose(fB, lane);
        float* ob = out + (size_t)branch * B * NTOK * DIM + (size_t)b * NTOK * DIM + h * HD;
        float* rA = ob + (mb + r0) * DIM + 8 * (lane & 3);
        *(float4*)rA = make_float4(fA[0].x, fA[0].y, fA[1].x, fA[1].y);
        *(float4*)(rA + 4) = make_float4(fA[2].x, fA[2].y, fA[3].x, fA[3].y);
        float* rB = rA + 8 * DIM;
        *(float4*)rB = make_float4(fB[0].x, fB[0].y, fB[1].x, fB[1].y);
        *(float4*)(rB + 4) = make_float4(fB[2].x, fB[2].y, fB[3].x, fB[3].y);
    }
}

// ---------------------------------------------------------------------------
extern "C" void kernel_launch(void* const* d_in, const int* in_sizes, int n_in,
                              void* d_out, int out_size) {
    const float* qkv     = (const float*)d_in[0];
    const float* ass_qkv = (const float*)d_in[1];
    const float* rel_pos = (const float*)d_in[2];
    const float* w1      = (const float*)d_in[3];
    const float* b1      = (const float*)d_in[4];
    const float* w2      = (const float*)d_in[5];
    const float* b2      = (const float*)d_in[6];
    float* out = (float*)d_out;

    const int B = in_sizes[0] / (NTOK * 3 * DIM);  // 2048

    cudaFuncSetAttribute(attn_kernel, cudaFuncAttributeMaxDynamicSharedMemorySize, SMEM_TOTAL);

    bias_kernel<<<32, 256>>>(rel_pos, w1, b1, w2, b2);
    attn_kernel<<<dim3(HEADS * 2, B), 128, SMEM_TOTAL>>>(qkv, ass_qkv, out, B);
}

// round 16
// speedup vs baseline: 1.1549x; 1.1549x over previous
#include <cuda_runtime.h>
#include <cuda_fp16.h>
#include <cstdint>

#define NTOK 64
#define HEADS 8
#define HD 32
#define DIM 256

typedef unsigned long long ull;

// bias in MMA-fragment layout: [h][row8(8)][nt(8)][r0(8)][c2pair(4)][2]
__device__ float g_bias[HEADS * NTOK * NTOK];

// ---------------- packed helpers ----------------
__device__ __forceinline__ ull ffma2(ull a, ull b, ull c) {
    ull d; asm("fma.rn.f32x2 %0, %1, %2, %3;" : "=l"(d) : "l"(a), "l"(b), "l"(c)); return d;
}
__device__ __forceinline__ ull dup2(float p) {
    ull r; asm("mov.b64 %0, {%1, %1};" : "=l"(r) : "f"(p)); return r;
}
__device__ __forceinline__ float2 u2f2(ull v) {
    float2 r; asm("mov.b64 {%0, %1}, %2;" : "=f"(r.x), "=f"(r.y) : "l"(v)); return r;
}
// fp16 pack: lo element in low half
__device__ __forceinline__ uint32_t f16pack(float lo, float hi) {
    uint32_t r; asm("cvt.rn.f16x2.f32 %0, %1, %2;" : "=r"(r) : "f"(hi), "f"(lo)); return r;
}
// fp16 hi/lo split of a float pair
__device__ __forceinline__ void split2h(float a0, float a1, uint32_t& hi, uint32_t& lo) {
    __half2 h = __float22half2_rn(make_float2(a0, a1));
    float2 back = __half22float2(h);
    __half2 l = __float22half2_rn(make_float2(a0 - back.x, a1 - back.y));
    hi = *reinterpret_cast<uint32_t*>(&h);
    lo = *reinterpret_cast<uint32_t*>(&l);
}
__device__ __forceinline__ uint32_t smem_u32(const void* p) {
    uint32_t a;
    asm("{ .reg .u64 t; cvta.to.shared.u64 t, %1; cvt.u32.u64 %0, t; }" : "=r"(a) : "l"(p));
    return a;
}

// ---------------- warp-mma primitives (baseline ISA) ----------------
__device__ __forceinline__ void ldsm4(uint32_t r[4], uint32_t a) {
    asm volatile("ldmatrix.sync.aligned.m8n8.x4.shared.b16 {%0,%1,%2,%3}, [%4];"
        : "=r"(r[0]), "=r"(r[1]), "=r"(r[2]), "=r"(r[3]) : "r"(a));
}
__device__ __forceinline__ void ldsm4t(uint32_t r[4], uint32_t a) {
    asm volatile("ldmatrix.sync.aligned.m8n8.x4.trans.shared.b16 {%0,%1,%2,%3}, [%4];"
        : "=r"(r[0]), "=r"(r[1]), "=r"(r[2]), "=r"(r[3]) : "r"(a));
}
__device__ __forceinline__ void mma16816h(float* c, const uint32_t* a, uint32_t b0, uint32_t b1) {
    asm volatile("mma.sync.aligned.m16n8k16.row.col.f32.f16.f16.f32 "
        "{%0,%1,%2,%3}, {%4,%5,%6,%7}, {%8,%9}, {%0,%1,%2,%3};"
        : "+f"(c[0]), "+f"(c[1]), "+f"(c[2]), "+f"(c[3])
        : "r"(a[0]), "r"(a[1]), "r"(a[2]), "r"(a[3]), "r"(b0), "r"(b1));
}

// smem tile geometry: [64 rows][80B rows]; chunks 0..3 (16B),
// stored at chunk' = chunk ^ ((row>>3)&3) -> conflict-free STS + LDSM.
// Q/K/V each single fp16 copy: 64 rows x 64B data in 80B rows = 5120 B.
#define Q_OFF 0
#define K_OFF 5120
#define V_OFF 10240
#define SMEM_TOTAL 15360

__device__ __forceinline__ uint32_t faddr(uint32_t base, int rowbase, int c0, int lane) {
    int row = rowbase + (lane & 15);
    int chunk = (c0 + (lane >> 4)) ^ ((row >> 3) & 3);
    return base + row * 80 + chunk * 16;
}

// ---------------------------------------------------------------------------
// Kernel 1: relative-position bias MLP -> g_bias (R14 fragment layout),
// 2-way k-split across thread pairs, shfl-reduced.
// ---------------------------------------------------------------------------
__global__ __launch_bounds__(256)
void bias_kernel(const float* __restrict__ rel_pos,
                 const float* __restrict__ w1,
                 const float* __restrict__ b1,
                 const float* __restrict__ w2,
                 const float* __restrict__ b2) {
    __shared__ float w1a[256], w1b[256], b1s[256];
    __shared__ float4 w2s[512];
    const int t = threadIdx.x;
    w1a[t] = w1[t];
    w1b[t] = w1[256 + t];
    b1s[t] = b1[t];
#pragma unroll
    for (int i = t; i < 512; i += 256)
        w2s[i] = ((const float4*)w2)[i];
    __syncthreads();

    const int half = t & 1;
    const int nm = blockIdx.x * 128 + (t >> 1);
    const int n = nm >> 6, m = nm & 63;
    const float r0 = rel_pos[2 * nm];
    const float r1 = rel_pos[2 * nm + 1];
    ull acc[4] = {0ull, 0ull, 0ull, 0ull};
    const ulonglong2* w2u = (const ulonglong2*)w2s;
    const int k0 = half * 128;
#pragma unroll 8
    for (int kk = 0; kk < 128; kk++) {
        const int k = k0 + kk;
        float hk = fmaxf(fmaf(r0, w1a[k], fmaf(r1, w1b[k], b1s[k])), 0.f);
        ull hd = dup2(hk);
        ulonglong2 wa = w2u[2 * k];
        ulonglong2 wb = w2u[2 * k + 1];
        acc[0] = ffma2(hd, wa.x, acc[0]);
        acc[1] = ffma2(hd, wa.y, acc[1]);
        acc[2] = ffma2(hd, wb.x, acc[2]);
        acc[3] = ffma2(hd, wb.y, acc[3]);
    }
    float s[8];
#pragma unroll
    for (int p = 0; p < 4; p++) {
        float2 v = u2f2(acc[p]);
        s[2 * p] = v.x;
        s[2 * p + 1] = v.y;
    }
#pragma unroll
    for (int p = 0; p < 8; p++)
        s[p] += __shfl_xor_sync(0xffffffffu, s[p], 1);
    if (!half) {
        // R14 fragment layout offset: [row8][nt][r0][m&7]
        const int off = (n >> 3) * 512 + (m >> 3) * 64 + (n & 7) * 8 + (m & 7);
#pragma unroll
        for (int p = 0; p < 8; p++)
            g_bias[p * (NTOK * NTOK) + off] = s[p] + b2[p];
    }
}

// ---------------------------------------------------------------------------
// Kernel 2: warp-mma attention. CTA=(b,h,branch), 4 warps = 4 m-quarters.
// S: single-fp16 q x k (1 product). PV: P fp16 hi/lo x fp16 V (2 products).
// Bias in R14 fragment layout (coalesced float2); scale folded into bias-FMA.
// ---------------------------------------------------------------------------
__global__ __launch_bounds__(128, 6)
void attn_kernel(const float* __restrict__ qkv,
                 const float* __restrict__ ass_qkv,
                 float* __restrict__ out, int B) {
    extern __shared__ char sm[];
    const int b = blockIdx.y;
    const int h = blockIdx.x >> 1;
    const int branch = blockIdx.x & 1;
    const int t = threadIdx.x;
    const int lane = t & 31, w = t >> 5;
    const float scale = 0.17677669529663687f;

    // ---- cooperative gmem -> smem (uniform fp16 pack, swizzled) ----
    {
        const float* srcb = (branch ? ass_qkv : qkv) + (size_t)b * (NTOK * 3 * DIM) + h * HD;
        const int f = t & 7;
        const int tokbase = t >> 3;          // 0..15
#pragma unroll
        for (int it = 0; it < 12; it++) {
            const int mat = it >> 2;
            const int tok = (it & 3) * 16 + tokbase;
            const float4 v = *(const float4*)(srcb + tok * (3 * DIM) + mat * DIM + f * 4);
            const int off = tok * 80 + 16 * ((f >> 1) ^ ((tok >> 3) & 3)) + 8 * (f & 1);
            uint32_t v01 = f16pack(v.x, v.y);
            uint32_t v23 = f16pack(v.z, v.w);
            *(uint2*)(sm + mat * 5120 + off) = make_uint2(v01, v23);
        }
    }
    __syncthreads();

    const int mb = w * 16;           // m-quarter base row
    const uint32_t sbase = smem_u32(sm);
    const uint32_t qq = sbase + Q_OFF;
    const uint32_t kk_ = sbase + K_OFF;
    const uint32_t vv = sbase + V_OFF;

    // ---- S = q @ k^T : 1 m16-tile x 8 n8-tiles, single fp16 product ----
    float sacc[8][4];
#pragma unroll
    for (int nt = 0; nt < 8; nt++)
#pragma unroll
        for (int c = 0; c < 4; c++) sacc[nt][c] = 0.f;

#pragma unroll
    for (int ks = 0; ks < 2; ks++) {
        uint32_t a4[4];
        ldsm4(a4, faddr(qq, mb, 2 * ks, lane));
#pragma unroll
        for (int g = 0; g < 4; g++) {
            uint32_t b4[4];
            ldsm4(b4, faddr(kk_, 16 * g, 2 * ks, lane));
            mma16816h(sacc[2 * g], a4, b4[0], b4[2]);
            mma16816h(sacc[2 * g + 1], a4, b4[1], b4[3]);
        }
    }

    // ---- bias (fragment layout, coalesced float2) + scale fold + softmax ----
    const int r0 = lane >> 2, c2 = (lane & 3) * 2;
    float inva, invb;
    {
        // lane-contiguous: float2 index = [row8][nt][r0*4 + (lane&3)]
        const float2* bp2 = (const float2*)(g_bias + h * (NTOK * NTOK) + (mb >> 3) * 512)
                            + (r0 * 4 + (lane & 3));
        float mxa = -1e30f, mxb = -1e30f;
#pragma unroll
        for (int nt = 0; nt < 8; nt++) {
            float2 ba = __ldg(bp2 + nt * 32);
            float2 bbv = __ldg(bp2 + 256 + nt * 32);
            sacc[nt][0] = fmaf(sacc[nt][0], scale, ba.x);
            sacc[nt][1] = fmaf(sacc[nt][1], scale, ba.y);
            sacc[nt][2] = fmaf(sacc[nt][2], scale, bbv.x);
            sacc[nt][3] = fmaf(sacc[nt][3], scale, bbv.y);
            mxa = fmaxf(mxa, fmaxf(sacc[nt][0], sacc[nt][1]));
            mxb = fmaxf(mxb, fmaxf(sacc[nt][2], sacc[nt][3]));
        }
        mxa = fmaxf(mxa, __shfl_xor_sync(0xffffffffu, mxa, 1));
        mxa = fmaxf(mxa, __shfl_xor_sync(0xffffffffu, mxa, 2));
        mxb = fmaxf(mxb, __shfl_xor_sync(0xffffffffu, mxb, 1));
        mxb = fmaxf(mxb, __shfl_xor_sync(0xffffffffu, mxb, 2));
        float sa = 0.f, sb = 0.f;
#pragma unroll
        for (int nt = 0; nt < 8; nt++) {
            sacc[nt][0] = __expf(sacc[nt][0] - mxa);
            sacc[nt][1] = __expf(sacc[nt][1] - mxa);
            sacc[nt][2] = __expf(sacc[nt][2] - mxb);
            sacc[nt][3] = __expf(sacc[nt][3] - mxb);
            sa += sacc[nt][0] + sacc[nt][1];
            sb += sacc[nt][2] + sacc[nt][3];
        }
        sa += __shfl_xor_sync(0xffffffffu, sa, 1);
        sa += __shfl_xor_sync(0xffffffffu, sa, 2);
        sb += __shfl_xor_sync(0xffffffffu, sb, 1);
        sb += __shfl_xor_sync(0xffffffffu, sb, 2);
        inva = __fdividef(1.0f, sa);
        invb = __fdividef(1.0f, sb);
    }

    // ---- O = P @ V : P fp16 hi/lo from registers, V fp16 via ldsm.trans ----
    float oacc[4][4];
#pragma unroll
    for (int dt = 0; dt < 4; dt++)
#pragma unroll
        for (int c = 0; c < 4; c++) oacc[dt][c] = 0.f;

#pragma unroll
    for (int kk = 0; kk < 4; kk++) {
        uint32_t ph[4], pl[4];
        split2h(sacc[2 * kk][0], sacc[2 * kk][1], ph[0], pl[0]);
        split2h(sacc[2 * kk][2], sacc[2 * kk][3], ph[1], pl[1]);
        split2h(sacc[2 * kk + 1][0], sacc[2 * kk + 1][1], ph[2], pl[2]);
        split2h(sacc[2 * kk + 1][2], sacc[2 * kk + 1][3], ph[3], pl[3]);
#pragma unroll
        for (int dg = 0; dg < 2; dg++) {
            uint32_t v4[4];
            ldsm4t(v4, faddr(vv, 16 * kk, 2 * dg, lane));
            mma16816h(oacc[2 * dg], ph, v4[0], v4[1]);
            mma16816h(oacc[2 * dg + 1], ph, v4[2], v4[3]);
            mma16816h(oacc[2 * dg], pl, v4[0], v4[1]);
            mma16816h(oacc[2 * dg + 1], pl, v4[2], v4[3]);
        }
    }

    // ---- normalize + store ----
    float* ob = out + (size_t)branch * B * NTOK * DIM + (size_t)b * NTOK * DIM + h * HD;
    const int rowA = mb + r0;
#pragma unroll
    for (int dt = 0; dt < 4; dt++) {
        const int d = dt * 8 + c2;
        *(float2*)(ob + rowA * DIM + d) =
            make_float2(oacc[dt][0] * inva, oacc[dt][1] * inva);
        *(float2*)(ob + (rowA + 8) * DIM + d) =
            make_float2(oacc[dt][2] * invb, oacc[dt][3] * invb);
    }
}

// ---------------------------------------------------------------------------
extern "C" void kernel_launch(void* const* d_in, const int* in_sizes, int n_in,
                              void* d_out, int out_size) {
    const float* qkv     = (const float*)d_in[0];
    const float* ass_qkv = (const float*)d_in[1];
    const float* rel_pos = (const float*)d_in[2];
    const float* w1      = (const float*)d_in[3];
    const float* b1      = (const float*)d_in[4];
    const float* w2      = (const float*)d_in[5];
    const float* b2      = (const float*)d_in[6];
    float* out = (float*)d_out;

    const int B = in_sizes[0] / (NTOK * 3 * DIM);  // 2048

    cudaFuncSetAttribute(attn_kernel, cudaFuncAttributeMaxDynamicSharedMemorySize, SMEM_TOTAL);

    bias_kernel<<<32, 256>>>(rel_pos, w1, b1, w2, b2);
    attn_kernel<<<dim3(HEADS * 2, B), 128, SMEM_TOTAL>>>(qkv, ass_qkv, out, B);
}

// round 17
// speedup vs baseline: 1.1621x; 1.0062x over previous
#include <cuda_runtime.h>
#include <cuda_fp16.h>
#include <cstdint>

#define NTOK 64
#define HEADS 8
#define HD 32
#define DIM 256

typedef unsigned long long ull;

// bias in MMA-fragment layout: [h][row8(8)][nt(8)][r0(8)][c2pair(4)][2]
__device__ float g_bias[HEADS * NTOK * NTOK];

// ---------------- packed helpers ----------------
__device__ __forceinline__ ull ffma2(ull a, ull b, ull c) {
    ull d; asm("fma.rn.f32x2 %0, %1, %2, %3;" : "=l"(d) : "l"(a), "l"(b), "l"(c)); return d;
}
__device__ __forceinline__ ull dup2(float p) {
    ull r; asm("mov.b64 %0, {%1, %1};" : "=l"(r) : "f"(p)); return r;
}
__device__ __forceinline__ float2 u2f2(ull v) {
    float2 r; asm("mov.b64 {%0, %1}, %2;" : "=f"(r.x), "=f"(r.y) : "l"(v)); return r;
}
// fp16 pack: lo element in low half
__device__ __forceinline__ uint32_t f16pack(float lo, float hi) {
    uint32_t r; asm("cvt.rn.f16x2.f32 %0, %1, %2;" : "=r"(r) : "f"(hi), "f"(lo)); return r;
}
// fp16 hi/lo split of a float pair
__device__ __forceinline__ void split2h(float a0, float a1, uint32_t& hi, uint32_t& lo) {
    __half2 h = __float22half2_rn(make_float2(a0, a1));
    float2 back = __half22float2(h);
    __half2 l = __float22half2_rn(make_float2(a0 - back.x, a1 - back.y));
    hi = *reinterpret_cast<uint32_t*>(&h);
    lo = *reinterpret_cast<uint32_t*>(&l);
}
__device__ __forceinline__ uint32_t smem_u32(const void* p) {
    uint32_t a;
    asm("{ .reg .u64 t; cvta.to.shared.u64 t, %1; cvt.u32.u64 %0, t; }" : "=r"(a) : "l"(p));
    return a;
}
__device__ __forceinline__ float2 shfl_xor_f2(float2 v, int m) {
    v.x = __shfl_xor_sync(0xffffffffu, v.x, m);
    v.y = __shfl_xor_sync(0xffffffffu, v.y, m);
    return v;
}
// 4x4 transpose across lane-quads: after, lane (quad, j) reg s = old lane (quad, s) reg j
__device__ __forceinline__ void quad_transpose(float2 f[4], int lane) {
    float2 s, r;
    s = (lane & 1) ? f[0] : f[1]; r = shfl_xor_f2(s, 1);
    if (lane & 1) f[0] = r; else f[1] = r;
    s = (lane & 1) ? f[2] : f[3]; r = shfl_xor_f2(s, 1);
    if (lane & 1) f[2] = r; else f[3] = r;
    s = (lane & 2) ? f[0] : f[2]; r = shfl_xor_f2(s, 2);
    if (lane & 2) f[0] = r; else f[2] = r;
    s = (lane & 2) ? f[1] : f[3]; r = shfl_xor_f2(s, 2);
    if (lane & 2) f[1] = r; else f[3] = r;
}

// ---------------- warp-mma primitives (baseline ISA) ----------------
__device__ __forceinline__ void ldsm4(uint32_t r[4], uint32_t a) {
    asm volatile("ldmatrix.sync.aligned.m8n8.x4.shared.b16 {%0,%1,%2,%3}, [%4];"
        : "=r"(r[0]), "=r"(r[1]), "=r"(r[2]), "=r"(r[3]) : "r"(a));
}
__device__ __forceinline__ void ldsm4t(uint32_t r[4], uint32_t a) {
    asm volatile("ldmatrix.sync.aligned.m8n8.x4.trans.shared.b16 {%0,%1,%2,%3}, [%4];"
        : "=r"(r[0]), "=r"(r[1]), "=r"(r[2]), "=r"(r[3]) : "r"(a));
}
__device__ __forceinline__ void mma16816h(float* c, const uint32_t* a, uint32_t b0, uint32_t b1) {
    asm volatile("mma.sync.aligned.m16n8k16.row.col.f32.f16.f16.f32 "
        "{%0,%1,%2,%3}, {%4,%5,%6,%7}, {%8,%9}, {%0,%1,%2,%3};"
        : "+f"(c[0]), "+f"(c[1]), "+f"(c[2]), "+f"(c[3])
        : "r"(a[0]), "r"(a[1]), "r"(a[2]), "r"(a[3]), "r"(b0), "r"(b1));
}

// smem tile geometry: [64 rows][80B rows]; chunks 0..3 (16B),
// stored at chunk' = chunk ^ ((row>>3)&3) -> conflict-free STS + LDSM.
// Q/K/V each single fp16 copy: 64 rows x 64B data in 80B rows = 5120 B.
#define Q_OFF 0
#define K_OFF 5120
#define V_OFF 10240
#define SMEM_TOTAL 15360

__device__ __forceinline__ uint32_t faddr(uint32_t base, int rowbase, int c0, int lane) {
    int row = rowbase + (lane & 15);
    int chunk = (c0 + (lane >> 4)) ^ ((row >> 3) & 3);
    return base + row * 80 + chunk * 16;
}

// ---------------------------------------------------------------------------
// Kernel 1: relative-position bias MLP -> g_bias (fragment layout),
// 2-way k-split across thread pairs, shfl-reduced.
// ---------------------------------------------------------------------------
__global__ __launch_bounds__(256)
void bias_kernel(const float* __restrict__ rel_pos,
                 const float* __restrict__ w1,
                 const float* __restrict__ b1,
                 const float* __restrict__ w2,
                 const float* __restrict__ b2) {
    __shared__ float w1a[256], w1b[256], b1s[256];
    __shared__ float4 w2s[512];
    const int t = threadIdx.x;
    w1a[t] = w1[t];
    w1b[t] = w1[256 + t];
    b1s[t] = b1[t];
#pragma unroll
    for (int i = t; i < 512; i += 256)
        w2s[i] = ((const float4*)w2)[i];
    __syncthreads();

    const int half = t & 1;
    const int nm = blockIdx.x * 128 + (t >> 1);
    const int n = nm >> 6, m = nm & 63;
    const float r0 = rel_pos[2 * nm];
    const float r1 = rel_pos[2 * nm + 1];
    ull acc[4] = {0ull, 0ull, 0ull, 0ull};
    const ulonglong2* w2u = (const ulonglong2*)w2s;
    const int k0 = half * 128;
#pragma unroll 8
    for (int kk = 0; kk < 128; kk++) {
        const int k = k0 + kk;
        float hk = fmaxf(fmaf(r0, w1a[k], fmaf(r1, w1b[k], b1s[k])), 0.f);
        ull hd = dup2(hk);
        ulonglong2 wa = w2u[2 * k];
        ulonglong2 wb = w2u[2 * k + 1];
        acc[0] = ffma2(hd, wa.x, acc[0]);
        acc[1] = ffma2(hd, wa.y, acc[1]);
        acc[2] = ffma2(hd, wb.x, acc[2]);
        acc[3] = ffma2(hd, wb.y, acc[3]);
    }
    float s[8];
#pragma unroll
    for (int p = 0; p < 4; p++) {
        float2 v = u2f2(acc[p]);
        s[2 * p] = v.x;
        s[2 * p + 1] = v.y;
    }
#pragma unroll
    for (int p = 0; p < 8; p++)
        s[p] += __shfl_xor_sync(0xffffffffu, s[p], 1);
    if (!half) {
        // fragment layout offset: [row8][nt][r0][m&7]
        const int off = (n >> 3) * 512 + (m >> 3) * 64 + (n & 7) * 8 + (m & 7);
#pragma unroll
        for (int p = 0; p < 8; p++)
            g_bias[p * (NTOK * NTOK) + off] = s[p] + b2[p];
    }
}

// ---------------------------------------------------------------------------
// Kernel 2: warp-mma attention. CTA=(b,h,branch), 4 warps = 4 m-quarters.
// S: single-fp16 q x k (1 product). PV: P fp16 hi/lo x fp16 V (2 products).
// Bias in fragment layout (coalesced float2); quad-transposed STG.128 epilogue.
// ---------------------------------------------------------------------------
__global__ __launch_bounds__(128, 6)
void attn_kernel(const float* __restrict__ qkv,
                 const float* __restrict__ ass_qkv,
                 float* __restrict__ out, int B) {
    extern __shared__ char sm[];
    const int b = blockIdx.y;
    const int h = blockIdx.x >> 1;
    const int branch = blockIdx.x & 1;
    const int t = threadIdx.x;
    const int lane = t & 31, w = t >> 5;
    const float scale = 0.17677669529663687f;

    // ---- cooperative gmem -> smem (uniform fp16 pack, swizzled) ----
    {
        const float* srcb = (branch ? ass_qkv : qkv) + (size_t)b * (NTOK * 3 * DIM) + h * HD;
        const int f = t & 7;
        const int tokbase = t >> 3;          // 0..15
#pragma unroll
        for (int it = 0; it < 12; it++) {
            const int mat = it >> 2;
            const int tok = (it & 3) * 16 + tokbase;
            const float4 v = *(const float4*)(srcb + tok * (3 * DIM) + mat * DIM + f * 4);
            const int off = tok * 80 + 16 * ((f >> 1) ^ ((tok >> 3) & 3)) + 8 * (f & 1);
            uint32_t v01 = f16pack(v.x, v.y);
            uint32_t v23 = f16pack(v.z, v.w);
            *(uint2*)(sm + mat * 5120 + off) = make_uint2(v01, v23);
        }
    }
    __syncthreads();

    const int mb = w * 16;           // m-quarter base row
    const uint32_t sbase = smem_u32(sm);
    const uint32_t qq = sbase + Q_OFF;
    const uint32_t kk_ = sbase + K_OFF;
    const uint32_t vv = sbase + V_OFF;

    // ---- S = q @ k^T : 1 m16-tile x 8 n8-tiles, single fp16 product ----
    float sacc[8][4];
#pragma unroll
    for (int nt = 0; nt < 8; nt++)
#pragma unroll
        for (int c = 0; c < 4; c++) sacc[nt][c] = 0.f;

#pragma unroll
    for (int ks = 0; ks < 2; ks++) {
        uint32_t a4[4];
        ldsm4(a4, faddr(qq, mb, 2 * ks, lane));
#pragma unroll
        for (int g = 0; g < 4; g++) {
            uint32_t b4[4];
            ldsm4(b4, faddr(kk_, 16 * g, 2 * ks, lane));
            mma16816h(sacc[2 * g], a4, b4[0], b4[2]);
            mma16816h(sacc[2 * g + 1], a4, b4[1], b4[3]);
        }
    }

    // ---- bias (fragment layout, coalesced float2) + scale fold + softmax ----
    const int r0 = lane >> 2, c2 = (lane & 3) * 2;
    float inva, invb;
    {
        // lane-contiguous: float2 index = [row8][nt][r0*4 + (lane&3)]
        const float2* bp2 = (const float2*)(g_bias + h * (NTOK * NTOK) + (mb >> 3) * 512)
                            + (r0 * 4 + (lane & 3));
        float mxa = -1e30f, mxb = -1e30f;
#pragma unroll
        for (int nt = 0; nt < 8; nt++) {
            float2 ba = __ldg(bp2 + nt * 32);
            float2 bbv = __ldg(bp2 + 256 + nt * 32);
            sacc[nt][0] = fmaf(sacc[nt][0], scale, ba.x);
            sacc[nt][1] = fmaf(sacc[nt][1], scale, ba.y);
            sacc[nt][2] = fmaf(sacc[nt][2], scale, bbv.x);
            sacc[nt][3] = fmaf(sacc[nt][3], scale, bbv.y);
            mxa = fmaxf(mxa, fmaxf(sacc[nt][0], sacc[nt][1]));
            mxb = fmaxf(mxb, fmaxf(sacc[nt][2], sacc[nt][3]));
        }
        mxa = fmaxf(mxa, __shfl_xor_sync(0xffffffffu, mxa, 1));
        mxa = fmaxf(mxa, __shfl_xor_sync(0xffffffffu, mxa, 2));
        mxb = fmaxf(mxb, __shfl_xor_sync(0xffffffffu, mxb, 1));
        mxb = fmaxf(mxb, __shfl_xor_sync(0xffffffffu, mxb, 2));
        float sa = 0.f, sb = 0.f;
#pragma unroll
        for (int nt = 0; nt < 8; nt++) {
            sacc[nt][0] = __expf(sacc[nt][0] - mxa);
            sacc[nt][1] = __expf(sacc[nt][1] - mxa);
            sacc[nt][2] = __expf(sacc[nt][2] - mxb);
            sacc[nt][3] = __expf(sacc[nt][3] - mxb);
            sa += sacc[nt][0] + sacc[nt][1];
            sb += sacc[nt][2] + sacc[nt][3];
        }
        sa += __shfl_xor_sync(0xffffffffu, sa, 1);
        sa += __shfl_xor_sync(0xffffffffu, sa, 2);
        sb += __shfl_xor_sync(0xffffffffu, sb, 1);
        sb += __shfl_xor_sync(0xffffffffu, sb, 2);
        inva = __fdividef(1.0f, sa);
        invb = __fdividef(1.0f, sb);
    }

    // ---- O = P @ V : P fp16 hi/lo from registers, V fp16 via ldsm.trans ----
    float oacc[4][4];
#pragma unroll
    for (int dt = 0; dt < 4; dt++)
#pragma unroll
        for (int c = 0; c < 4; c++) oacc[dt][c] = 0.f;

#pragma unroll
    for (int kk = 0; kk < 4; kk++) {
        uint32_t ph[4], pl[4];
        split2h(sacc[2 * kk][0], sacc[2 * kk][1], ph[0], pl[0]);
        split2h(sacc[2 * kk][2], sacc[2 * kk][3], ph[1], pl[1]);
        split2h(sacc[2 * kk + 1][0], sacc[2 * kk + 1][1], ph[2], pl[2]);
        split2h(sacc[2 * kk + 1][2], sacc[2 * kk + 1][3], ph[3], pl[3]);
#pragma unroll
        for (int dg = 0; dg < 2; dg++) {
            uint32_t v4[4];
            ldsm4t(v4, faddr(vv, 16 * kk, 2 * dg, lane));
            mma16816h(oacc[2 * dg], ph, v4[0], v4[1]);
            mma16816h(oacc[2 * dg + 1], ph, v4[2], v4[3]);
            mma16816h(oacc[2 * dg], pl, v4[0], v4[1]);
            mma16816h(oacc[2 * dg + 1], pl, v4[2], v4[3]);
        }
    }

    // ---- normalize + quad-transpose + coalesced STG.128 store ----
    {
        float2 fA[4], fB[4];
#pragma unroll
        for (int dt = 0; dt < 4; dt++) {
            fA[dt] = make_float2(oacc[dt][0] * inva, oacc[dt][1] * inva);
            fB[dt] = make_float2(oacc[dt][2] * invb, oacc[dt][3] * invb);
        }
        quad_transpose(fA, lane);
        quad_transpose(fB, lane);
        float* ob = out + (size_t)branch * B * NTOK * DIM + (size_t)b * NTOK * DIM + h * HD;
        float* rA = ob + (mb + r0) * DIM + 8 * (lane & 3);
        *(float4*)rA = make_float4(fA[0].x, fA[0].y, fA[1].x, fA[1].y);
        *(float4*)(rA + 4) = make_float4(fA[2].x, fA[2].y, fA[3].x, fA[3].y);
        float* rB = rA + 8 * DIM;
        *(float4*)rB = make_float4(fB[0].x, fB[0].y, fB[1].x, fB[1].y);
        *(float4*)(rB + 4) = make_float4(fB[2].x, fB[2].y, fB[3].x, fB[3].y);
    }
}

// ---------------------------------------------------------------------------
extern "C" void kernel_launch(void* const* d_in, const int* in_sizes, int n_in,
                              void* d_out, int out_size) {
    const float* qkv     = (const float*)d_in[0];
    const float* ass_qkv = (const float*)d_in[1];
    const float* rel_pos = (const float*)d_in[2];
    const float* w1      = (const float*)d_in[3];
    const float* b1      = (const float*)d_in[4];
    const float* w2      = (const float*)d_in[5];
    const float* b2      = (const float*)d_in[6];
    float* out = (float*)d_out;

    const int B = in_sizes[0] / (NTOK * 3 * DIM);  // 2048

    cudaFuncSetAttribute(attn_kernel, cudaFuncAttributeMaxDynamicSharedMemorySize, SMEM_TOTAL);

    bias_kernel<<<32, 256>>>(rel_pos, w1, b1, w2, b2);
    attn_kernel<<<dim3(HEADS * 2, B), 128, SMEM_TOTAL>>>(qkv, ass_qkv, out, B);
}